// round 14
// baseline (speedup 1.0000x reference)
#include <cuda_runtime.h>

#define NN 10000
#define NE 320000
#define HD 64
#define NLAYERS 4
#define TE 128   // edges per tile (edge kernel)
#define TNN 64   // nodes per tile (node/proj kernels)

typedef unsigned long long ull;

// ---------------- scratch state (allocation-free) ----------------
__device__ __align__(16) float g_h[NN * HD];
__device__ __align__(16) float g_agg[NN * HD];
__device__ __align__(16) float g_pa[NN * HD];    // h @ W1[0:64]
__device__ __align__(16) float g_pb[NN * HD];    // h @ W1[64:128]
__device__ __align__(16) float g_acc4[NN * 4];   // [dx,dy,dz,cnt] per node
__device__ float g_x[NN * 3];
__device__ float g_v[NN * 3];
__device__ float g_iv[NN * 3];
__device__ float g_zero64[64];                   // zero-initialized
__device__ int g_edge64;
// sorted-edge scratch
__device__ int g_er[NE];
__device__ int g_ec[NE];
__device__ __align__(8) float g_ea[NE * 2];
__device__ int g_hist[NN];
__device__ int g_cur[NN];

__device__ __forceinline__ float silu_f(float x) {
    return __fdividef(x, 1.0f + __expf(-x));
}

// packed f32x2 helpers
__device__ __forceinline__ ull d2(float x) {
    ull r;
    unsigned u = __float_as_uint(x);
    asm("mov.b64 %0, {%1, %1};" : "=l"(r) : "r"(u));
    return r;
}
__device__ __forceinline__ ull ffma2(ull a, ull b, ull c) {
    ull d;
    asm("fma.rn.f32x2 %0, %1, %2, %3;" : "=l"(d) : "l"(a), "l"(b), "l"(c));
    return d;
}
__device__ __forceinline__ float2 u2f(ull v) {
    unsigned lo, hi;
    asm("mov.b64 {%0, %1}, %2;" : "=r"(lo), "=r"(hi) : "l"(v));
    return make_float2(__uint_as_float(lo), __uint_as_float(hi));
}

// 16B vector reduction (sm_90+)
__device__ __forceinline__ void red4(float* p, float a, float b, float c, float d) {
    asm volatile("red.global.add.v4.f32 [%0], {%1, %2, %3, %4};"
                 :: "l"(p), "f"(a), "f"(b), "f"(c), "f"(d) : "memory");
}

// swizzled staging index (16B-granule xor)
__device__ __forceinline__ int sidx(int k, int e, int RW) {
    return k * RW + ((((e >> 2) ^ ((k >> 2) & 7)) << 2) | (e & 3));
}

__device__ __forceinline__ int edge_idx(const void* edges, long long i) {
    if (g_edge64) return (int)((const long long*)edges)[i];
    return ((const int*)edges)[i];
}

__global__ void k_detect(const void* edges) {
    const int* p = (const int*)edges;
    int is64 = 1;
    for (int i = 1; i < 64; i += 2)
        if (p[i] != 0) is64 = 0;
    g_edge64 = is64;
}

// ---------------- counting sort by row ----------------
__global__ void k_zhist() {
    int i = blockIdx.x * blockDim.x + threadIdx.x;
    if (i < NN) g_hist[i] = 0;
}
__global__ void k_count(const void* __restrict__ edges) {
    int i = blockIdx.x * blockDim.x + threadIdx.x;
    if (i < NE) atomicAdd(&g_hist[edge_idx(edges, i)], 1);
}
__global__ void k_scan() {   // 1 block, 1024 threads
    __shared__ int ws[32];
    __shared__ int carry_s;
    int t = threadIdx.x, lane = t & 31, w = t >> 5;
    if (t == 0) carry_s = 0;
    __syncthreads();
    for (int base = 0; base < NN; base += 1024) {
        int cbase = carry_s;
        int v = (base + t < NN) ? g_hist[base + t] : 0;
        int x = v;
#pragma unroll
        for (int d = 1; d < 32; d <<= 1) {
            int y = __shfl_up_sync(0xffffffffu, x, d);
            if (lane >= d) x += y;
        }
        if (lane == 31) ws[w] = x;
        __syncthreads();
        if (w == 0) {
            int s = ws[lane];
#pragma unroll
            for (int d = 1; d < 32; d <<= 1) {
                int y = __shfl_up_sync(0xffffffffu, s, d);
                if (lane >= d) s += y;
            }
            ws[lane] = s;
        }
        __syncthreads();
        int incl = x + (w ? ws[w - 1] : 0);
        if (base + t < NN) g_cur[base + t] = cbase + incl - v;
        __syncthreads();
        if (t == 0) carry_s = cbase + ws[31];
        __syncthreads();
    }
}
__global__ void k_permute(const void* __restrict__ edges, const float* __restrict__ ea) {
    int i = blockIdx.x * blockDim.x + threadIdx.x;
    if (i < NE) {
        int r = edge_idx(edges, i);
        int c = edge_idx(edges, (long long)NE + i);
        int pos = atomicAdd(&g_cur[r], 1);
        g_er[pos] = r;
        g_ec[pos] = c;
        float2 v = *(const float2*)&ea[2 * i];
        *(float2*)&g_ea[2 * pos] = v;
    }
}

__global__ void k_init(const float* __restrict__ his, const float* __restrict__ loc,
                       const float* __restrict__ vel, const float* __restrict__ emb_w,
                       const float* __restrict__ emb_b) {
    int idx = blockIdx.x * blockDim.x + threadIdx.x;
    if (idx < NN * HD) {
        int n = idx >> 6, j = idx & 63;
        float a = emb_b[j];
#pragma unroll
        for (int i = 0; i < 4; i++) a = fmaf(his[n * 4 + i], emb_w[i * 64 + j], a);
        g_h[idx] = a;
        g_agg[idx] = 0.f;
    }
    if (idx < NN * 4) g_acc4[idx] = 0.f;
    if (idx < NN * 3) {
        g_x[idx] = loc[idx];
        g_v[idx] = vel[idx];
    }
    if (idx < NN) {
        float vx = vel[idx * 3], vy = vel[idx * 3 + 1], vz = vel[idx * 3 + 2];
        float inv = 1.0f / (sqrtf(vx * vx + vy * vy + vz * vz) + 1e-8f);
        g_iv[idx * 3] = vx * inv;
        g_iv[idx * 3 + 1] = vy * inv;
        g_iv[idx * 3 + 2] = vz * inv;
    }
}

// ---- edge GEMM (R9-proven): warp owns feature octet; W via warp-uniform global LDG ----
template <int RW>
__device__ __forceinline__ void gemm_g(const float* __restrict__ st,
                                       const float* __restrict__ w,
                                       const float* __restrict__ bias,
                                       ull (&acc)[8][2], int wf, int lp, int K) {
#pragma unroll
    for (int j = 0; j < 8; j++) {
        ull bb = d2(bias[8 * wf + j]);
        acc[j][0] = bb;
        acc[j][1] = bb;
    }
    const float* wp = w + 8 * wf;
    for (int k0 = 0; k0 < K; k0 += 4) {
        int s = (k0 >> 2) & 7;
        int o = ((lp ^ s) << 2);
#pragma unroll
        for (int kk = 0; kk < 4; kk++) {
            ulonglong2 a = *(const ulonglong2*)(st + (k0 + kk) * RW + o);
            const float* wr = wp + (k0 + kk) * 64;
            float4 w0 = *(const float4*)(wr);
            float4 w1 = *(const float4*)(wr + 4);
            ull b0 = d2(w0.x), b1 = d2(w0.y), b2 = d2(w0.z), b3 = d2(w0.w);
            ull b4 = d2(w1.x), b5 = d2(w1.y), b6 = d2(w1.z), b7 = d2(w1.w);
            acc[0][0] = ffma2(a.x, b0, acc[0][0]);
            acc[0][1] = ffma2(a.y, b0, acc[0][1]);
            acc[1][0] = ffma2(a.x, b1, acc[1][0]);
            acc[1][1] = ffma2(a.y, b1, acc[1][1]);
            acc[2][0] = ffma2(a.x, b2, acc[2][0]);
            acc[2][1] = ffma2(a.y, b2, acc[2][1]);
            acc[3][0] = ffma2(a.x, b3, acc[3][0]);
            acc[3][1] = ffma2(a.y, b3, acc[3][1]);
            acc[4][0] = ffma2(a.x, b4, acc[4][0]);
            acc[4][1] = ffma2(a.y, b4, acc[4][1]);
            acc[5][0] = ffma2(a.x, b5, acc[5][0]);
            acc[5][1] = ffma2(a.y, b5, acc[5][1]);
            acc[6][0] = ffma2(a.x, b6, acc[6][0]);
            acc[6][1] = ffma2(a.y, b6, acc[6][1]);
            acc[7][0] = ffma2(a.x, b7, acc[7][0]);
            acc[7][1] = ffma2(a.y, b7, acc[7][1]);
        }
    }
}

// ---------------- edge kernel: sorted 128-edge tiles, register scatter ----------------
__global__ void __launch_bounds__(256, 3)
    k_edge(const float* __restrict__ ew1, const float* __restrict__ eb1,
           const float* __restrict__ ew2, const float* __restrict__ eb2,
           const float* __restrict__ cw1, const float* __restrict__ cb1,
           const float* __restrict__ cw2) {
    extern __shared__ __align__(16) float sm[];
    float* ins = sm;                    // 64*128 = 8192
    float* part = ins + 8192;           // 8*128 gate partials
    float* wtl = part + 1024;           // 64*4: {wr, wa0, wa1, b1} per k
    float* b2s = wtl + 256;             // 64
    float* b3s = b2s + 64;
    float* c2s = b3s + 64;
    float* cds = c2s + 64;              // 3*128
    int* rs = (int*)(cds + 384);        // 128

    const int tid = threadIdx.x;
    const int lane = tid & 31;
    const int wf = tid >> 5;            // feature octet = warp 0..7
    const int lp = lane;                // edge granule (edges 4lp..4lp+3)
    const int e = tid & 127;
    const int which = tid >> 7;         // k-half 0/1 for stage

    if (tid < 64) {
        wtl[tid * 4 + 0] = ew1[128 * 64 + tid];   // radial row
        wtl[tid * 4 + 1] = ew1[129 * 64 + tid];   // eattr row 0
        wtl[tid * 4 + 2] = ew1[130 * 64 + tid];   // eattr row 1
        wtl[tid * 4 + 3] = eb1[tid];
        b2s[tid] = eb2[tid];
        b3s[tid] = cb1[tid];
        c2s[tid] = cw2[tid];
    }

    const int ntile = NE / TE;
    for (int t = blockIdx.x; t < ntile; t += gridDim.x) {
        __syncthreads();
        int e0 = t * TE;
        int r = g_er[e0 + e];
        int c = g_ec[e0 + e];
        if (which == 0) rs[e] = r;

        // stage t1 = silu(Pa[row] + Pb[col] + rad*wr + ea@we + b1); 2 threads/edge
        float dx = g_x[r * 3] - g_x[c * 3];
        float dy = g_x[r * 3 + 1] - g_x[c * 3 + 1];
        float dz = g_x[r * 3 + 2] - g_x[c * 3 + 2];
        float rad = dx * dx + dy * dy + dz * dz;
        float2 ea = *(const float2*)&g_ea[(e0 + e) * 2];
        if (which == 0) {
            cds[e] = dx;
            cds[128 + e] = dy;
            cds[256 + e] = dz;
        }
        {
            const float4* pa = (const float4*)&g_pa[r * 64 + which * 32];
            const float4* pb = (const float4*)&g_pb[c * 64 + which * 32];
#pragma unroll
            for (int q = 0; q < 8; q++) {
                int k = which * 32 + 4 * q;
                float4 va = pa[q], vb = pb[q];
                float4 t0 = *(const float4*)&wtl[(k + 0) * 4];
                float4 t1 = *(const float4*)&wtl[(k + 1) * 4];
                float4 t2 = *(const float4*)&wtl[(k + 2) * 4];
                float4 t3 = *(const float4*)&wtl[(k + 3) * 4];
                float v0 = va.x + vb.x + rad * t0.x + ea.x * t0.y + ea.y * t0.z + t0.w;
                float v1 = va.y + vb.y + rad * t1.x + ea.x * t1.y + ea.y * t1.z + t1.w;
                float v2 = va.z + vb.z + rad * t2.x + ea.x * t2.y + ea.y * t2.z + t2.w;
                float v3 = va.w + vb.w + rad * t3.x + ea.x * t3.y + ea.y * t3.z + t3.w;
                ins[sidx(k + 0, e, 128)] = silu_f(v0);
                ins[sidx(k + 1, e, 128)] = silu_f(v1);
                ins[sidx(k + 2, e, 128)] = silu_f(v2);
                ins[sidx(k + 3, e, 128)] = silu_f(v3);
            }
        }
        __syncthreads();

        ull acc[8][2];
        // GEMM2: t1@[64,64] + b2 -> ef pre-activation in regs
        gemm_g<128>(ins, ew2, b2s, acc, wf, lp, 64);

        // silu once into registers: sv[edge 0..3][feature 0..7]
        float sv[4][8];
#pragma unroll
        for (int j = 0; j < 8; j++) {
            float2 f0 = u2f(acc[j][0]), f1 = u2f(acc[j][1]);
            sv[0][j] = silu_f(f0.x);
            sv[1][j] = silu_f(f0.y);
            sv[2][j] = silu_f(f1.x);
            sv[3][j] = silu_f(f1.y);
        }
        __syncthreads();
        // store ef for GEMM3 input
#pragma unroll
        for (int j = 0; j < 8; j++) {
            int rr = 8 * wf + j;
            int s = (rr >> 2) & 7;
            *(float4*)(ins + rr * 128 + ((lp ^ s) << 2)) =
                make_float4(sv[0][j], sv[1][j], sv[2][j], sv[3][j]);
        }
        // direct register scatter of agg (fire-and-forget, overlaps GEMM3):
        // thread owns features 8wf..8wf+7 of 4 consecutive row-sorted edges
        {
            int rr0 = rs[4 * lp + 0], rr1 = rs[4 * lp + 1];
            int rr2 = rs[4 * lp + 2], rr3 = rs[4 * lp + 3];
            int base = 8 * wf;
            float4 A = make_float4(sv[0][0], sv[0][1], sv[0][2], sv[0][3]);
            float4 B = make_float4(sv[0][4], sv[0][5], sv[0][6], sv[0][7]);
            int rprev = rr0;
            int rcur[3] = {rr1, rr2, rr3};
#pragma unroll
            for (int p = 1; p < 4; p++) {
                int rn = rcur[p - 1];
                if (rn != rprev) {
                    red4(&g_agg[rprev * 64 + base], A.x, A.y, A.z, A.w);
                    red4(&g_agg[rprev * 64 + base + 4], B.x, B.y, B.z, B.w);
                    A = make_float4(sv[p][0], sv[p][1], sv[p][2], sv[p][3]);
                    B = make_float4(sv[p][4], sv[p][5], sv[p][6], sv[p][7]);
                    rprev = rn;
                } else {
                    A.x += sv[p][0];
                    A.y += sv[p][1];
                    A.z += sv[p][2];
                    A.w += sv[p][3];
                    B.x += sv[p][4];
                    B.y += sv[p][5];
                    B.z += sv[p][6];
                    B.w += sv[p][7];
                }
            }
            red4(&g_agg[rprev * 64 + base], A.x, A.y, A.z, A.w);
            red4(&g_agg[rprev * 64 + base + 4], B.x, B.y, B.z, B.w);
        }
        __syncthreads();

        // GEMM3: ef@cw1 + b3, silu, dot cw2 -> per-warp gate partials
        gemm_g<128>(ins, cw1, b3s, acc, wf, lp, 64);
        {
            float g0 = 0.f, g1 = 0.f, g2 = 0.f, g3 = 0.f;
#pragma unroll
            for (int j = 0; j < 8; j++) {
                float cj = c2s[8 * wf + j];
                float2 f0 = u2f(acc[j][0]), f1 = u2f(acc[j][1]);
                g0 = fmaf(silu_f(f0.x), cj, g0);
                g1 = fmaf(silu_f(f0.y), cj, g1);
                g2 = fmaf(silu_f(f1.x), cj, g2);
                g3 = fmaf(silu_f(f1.y), cj, g3);
            }
            *(float4*)(part + wf * 128 + 4 * lp) = make_float4(g0, g1, g2, g3);
        }
        __syncthreads();

        // gate scatter with run-length pre-reduction (16 threads)
        if (tid < 16) {
            int oct = tid;
            int rprev = rs[oct * 8];
            float4 a4 = make_float4(0.f, 0.f, 0.f, 0.f);
#pragma unroll
            for (int j = 0; j < 8; j++) {
                int ee = oct * 8 + j;
                int rrn = rs[ee];
                float gg = 0.f;
#pragma unroll
                for (int w8 = 0; w8 < 8; w8++) gg += part[w8 * 128 + ee];
                float gx = cds[ee] * gg, gy = cds[128 + ee] * gg, gz = cds[256 + ee] * gg;
                if (rrn != rprev) {
                    red4(&g_acc4[rprev * 4], a4.x, a4.y, a4.z, a4.w);
                    a4 = make_float4(gx, gy, gz, 1.0f);
                    rprev = rrn;
                } else {
                    a4.x += gx;
                    a4.y += gy;
                    a4.z += gz;
                    a4.w += 1.0f;
                }
            }
            red4(&g_acc4[rprev * 4], a4.x, a4.y, a4.z, a4.w);
        }
    }
}

// ======== 4-pair GEMM micro-kernel (node/proj; RW=64) ========
template <int RW>
__device__ __forceinline__ void gemm_t(const float* __restrict__ st,
                                       const float* __restrict__ w,
                                       const float* __restrict__ bias,
                                       ull (&acc)[4][4], int fc, int er, int K) {
#pragma unroll
    for (int j = 0; j < 4; j++) {
        ull bb = d2(bias[4 * fc + j]);
#pragma unroll
        for (int p = 0; p < 4; p++) acc[p][j] = bb;
    }
    const int eg0 = 2 * er, eg1 = 2 * er + 1;
#pragma unroll 2
    for (int k0 = 0; k0 < K; k0 += 4) {
        int ss = (k0 >> 2) & 7;
        int o0 = ((eg0 ^ ss) << 2), o1 = ((eg1 ^ ss) << 2);
#pragma unroll
        for (int kk = 0; kk < 4; kk++) {
            const float* rp = st + (k0 + kk) * RW;
            ulonglong2 aA = *(const ulonglong2*)(rp + o0);
            ulonglong2 aB = *(const ulonglong2*)(rp + o1);
            float4 wv = *(const float4*)(w + (k0 + kk) * 64 + 4 * fc);
            ull b0 = d2(wv.x), b1 = d2(wv.y), b2 = d2(wv.z), b3 = d2(wv.w);
            acc[0][0] = ffma2(aA.x, b0, acc[0][0]);
            acc[1][0] = ffma2(aA.y, b0, acc[1][0]);
            acc[2][0] = ffma2(aB.x, b0, acc[2][0]);
            acc[3][0] = ffma2(aB.y, b0, acc[3][0]);
            acc[0][1] = ffma2(aA.x, b1, acc[0][1]);
            acc[1][1] = ffma2(aA.y, b1, acc[1][1]);
            acc[2][1] = ffma2(aB.x, b1, acc[2][1]);
            acc[3][1] = ffma2(aB.y, b1, acc[3][1]);
            acc[0][2] = ffma2(aA.x, b2, acc[0][2]);
            acc[1][2] = ffma2(aA.y, b2, acc[1][2]);
            acc[2][2] = ffma2(aB.x, b2, acc[2][2]);
            acc[3][2] = ffma2(aB.y, b2, acc[3][2]);
            acc[0][3] = ffma2(aA.x, b3, acc[0][3]);
            acc[1][3] = ffma2(aA.y, b3, acc[1][3]);
            acc[2][3] = ffma2(aB.x, b3, acc[2][3]);
            acc[3][3] = ffma2(aB.y, b3, acc[3][3]);
        }
    }
}

template <int RW>
__device__ __forceinline__ void store_silu_t4(float* st, ull (&acc)[4][4], int fc, int er) {
    int ss = fc & 7;
    int o0 = (((2 * er) ^ ss) << 2), o1 = (((2 * er + 1) ^ ss) << 2);
#pragma unroll
    for (int j = 0; j < 4; j++) {
        int r = 4 * fc + j;
        float2 f0 = u2f(acc[0][j]), f1 = u2f(acc[1][j]);
        float2 f2 = u2f(acc[2][j]), f3 = u2f(acc[3][j]);
        float4 v0 = make_float4(silu_f(f0.x), silu_f(f0.y), silu_f(f1.x), silu_f(f1.y));
        float4 v1 = make_float4(silu_f(f2.x), silu_f(f2.y), silu_f(f3.x), silu_f(f3.y));
        *(float4*)(st + r * RW + o0) = v0;
        *(float4*)(st + r * RW + o1) = v1;
    }
}

// ---------------- proj kernel (initial only) ----------------
__global__ void __launch_bounds__(128, 2)
    k_proj(const float* __restrict__ ew1) {
    extern __shared__ __align__(16) float sm[];
    float* us = sm;             // 64*64

    const int tid = threadIdx.x;
    const int fc = tid & 15;
    const int er = tid >> 4;
    const int e = tid & 63;
    const int half = tid >> 6;

    const int ntile = (NN + TNN - 1) / TNN;
    for (int t = blockIdx.x; t < ntile; t += gridDim.x) {
        __syncthreads();
        int n0 = t * TNN;
        int n = n0 + e;
#pragma unroll
        for (int q = 0; q < 8; q++) {
            int kq = half * 8 + q;
            float4 hv = make_float4(0, 0, 0, 0);
            if (n < NN) hv = *(const float4*)&g_h[n * 64 + 4 * kq];
            us[sidx(4 * kq + 0, e, 64)] = hv.x;
            us[sidx(4 * kq + 1, e, 64)] = hv.y;
            us[sidx(4 * kq + 2, e, 64)] = hv.z;
            us[sidx(4 * kq + 3, e, 64)] = hv.w;
        }
        __syncthreads();

        ull acc[4][4];
        gemm_t<64>(us, ew1, g_zero64, acc, fc, er, 64);
#pragma unroll
        for (int p = 0; p < 4; p++) {
            int nlo = n0 + 8 * er + 2 * p, nhi = nlo + 1;
#pragma unroll
            for (int j = 0; j < 4; j++) {
                float2 f = u2f(acc[p][j]);
                if (nlo < NN) g_pa[nlo * 64 + 4 * fc + j] = f.x;
                if (nhi < NN) g_pa[nhi * 64 + 4 * fc + j] = f.y;
            }
        }
        gemm_t<64>(us, ew1 + 4096, g_zero64, acc, fc, er, 64);
#pragma unroll
        for (int p = 0; p < 4; p++) {
            int nlo = n0 + 8 * er + 2 * p, nhi = nlo + 1;
#pragma unroll
            for (int j = 0; j < 4; j++) {
                float2 f = u2f(acc[p][j]);
                if (nlo < NN) g_pb[nlo * 64 + 4 * fc + j] = f.x;
                if (nhi < NN) g_pb[nhi * 64 + 4 * fc + j] = f.y;
            }
        }
    }
}

// ---------------- node kernel (R9 proven): node MLPs + update + fused proj ----------------
__global__ void __launch_bounds__(128, 2)
    k_node(const float* __restrict__ nw1, const float* __restrict__ nb1,
           const float* __restrict__ nw2, const float* __restrict__ nb2,
           const float* __restrict__ vw1, const float* __restrict__ vb1,
           const float* __restrict__ vw2, const float* __restrict__ vb2,
           const float* __restrict__ ew1) {
    extern __shared__ __align__(16) float sm[];
    float* wn1 = sm;
    float* wn2 = wn1 + 8192;
    float* wv1 = wn2 + 4096;
    float* us = wv1 + 4096;
    float* nb1s = us + 8192;
    float* nb2s = nb1s + 64;
    float* vb1s = nb2s + 64;
    float* vw2s = vb1s + 64;
    float* phis = vw2s + 64;

    const int tid = threadIdx.x;
    const int fc = tid & 15;
    const int er = tid >> 4;

    for (int i = tid; i < 2048; i += 128) ((float4*)wn1)[i] = ((const float4*)nw1)[i];
    for (int i = tid; i < 1024; i += 128) {
        ((float4*)wn2)[i] = ((const float4*)nw2)[i];
        ((float4*)wv1)[i] = ((const float4*)vw1)[i];
    }
    if (tid < 64) {
        nb1s[tid] = nb1[tid];
        nb2s[tid] = nb2[tid];
        vb1s[tid] = vb1[tid];
        vw2s[tid] = vw2[tid];
    }
    const float vb2v = vb2[0];

    const int e = tid & 63;
    const int half = tid >> 6;
    const int ntile = (NN + TNN - 1) / TNN;
    for (int t = blockIdx.x; t < ntile; t += gridDim.x) {
        __syncthreads();
        int n0 = t * TNN;
        int n = n0 + e;
#pragma unroll
        for (int q = 0; q < 8; q++) {
            int kq = half * 8 + q;
            float4 hv = make_float4(0, 0, 0, 0), av = make_float4(0, 0, 0, 0);
            if (n < NN) {
                hv = *(const float4*)&g_h[n * 64 + 4 * kq];
                av = *(const float4*)&g_agg[n * 64 + 4 * kq];
            }
            us[sidx(4 * kq + 0, e, 64)] = hv.x;
            us[sidx(4 * kq + 1, e, 64)] = hv.y;
            us[sidx(4 * kq + 2, e, 64)] = hv.z;
            us[sidx(4 * kq + 3, e, 64)] = hv.w;
            us[sidx(64 + 4 * kq + 0, e, 64)] = av.x;
            us[sidx(64 + 4 * kq + 1, e, 64)] = av.y;
            us[sidx(64 + 4 * kq + 2, e, 64)] = av.z;
            us[sidx(64 + 4 * kq + 3, e, 64)] = av.w;
        }
        __syncthreads();

        ull acc[4][4];
        // vel MLP
        gemm_t<64>(us, wv1, vb1s, acc, fc, er, 64);
        {
            float gv[8] = {0.f, 0.f, 0.f, 0.f, 0.f, 0.f, 0.f, 0.f};
#pragma unroll
            for (int p = 0; p < 4; p++)
#pragma unroll
                for (int j = 0; j < 4; j++) {
                    float2 f = u2f(acc[p][j]);
                    float cj = vw2s[4 * fc + j];
                    gv[2 * p] = fmaf(silu_f(f.x), cj, gv[2 * p]);
                    gv[2 * p + 1] = fmaf(silu_f(f.y), cj, gv[2 * p + 1]);
                }
#pragma unroll
            for (int m = 1; m < 16; m <<= 1)
#pragma unroll
                for (int i = 0; i < 8; i++)
                    gv[i] += __shfl_xor_sync(0xffffffffu, gv[i], m);
            if (fc == 0)
#pragma unroll
                for (int i = 0; i < 8; i++) phis[8 * er + i] = gv[i] + vb2v;
        }

        // node GEMM1
        gemm_t<64>(us, wn1, nb1s, acc, fc, er, 128);
        __syncthreads();
        store_silu_t4<64>(us + 64 * 64, acc, fc, er);
        __syncthreads();

        // node GEMM2 -> hn; h += hn; restage h_new
        gemm_t<64>(us + 64 * 64, wn2, nb2s, acc, fc, er, 64);
#pragma unroll
        for (int p = 0; p < 4; p++) {
            int nlo = n0 + 8 * er + 2 * p, nhi = nlo + 1;
#pragma unroll
            for (int j = 0; j < 4; j++) {
                float2 f = u2f(acc[p][j]);
                if (nlo < NN) {
                    float hx = g_h[nlo * 64 + 4 * fc + j] + f.x;
                    g_h[nlo * 64 + 4 * fc + j] = hx;
                    us[sidx(4 * fc + j, 8 * er + 2 * p, 64)] = hx;
                }
                if (nhi < NN) {
                    float hx = g_h[nhi * 64 + 4 * fc + j] + f.y;
                    g_h[nhi * 64 + 4 * fc + j] = hx;
                    us[sidx(4 * fc + j, 8 * er + 2 * p + 1, 64)] = hx;
                }
            }
        }

        // per-node coord/vel update + zero scratch
        if (tid < TNN) {
            int nu = n0 + tid;
            if (nu < NN) {
                float cnt = g_acc4[nu * 4 + 3];
                float inv = 1.0f / fmaxf(cnt, 1.0f);
                float phi = phis[tid];
#pragma unroll
                for (int d = 0; d < 3; d++) {
                    float a = g_acc4[nu * 4 + d] * inv;
                    float vn = g_v[nu * 3 + d] + a + phi * g_iv[nu * 3 + d];
                    g_v[nu * 3 + d] = vn;
                    g_x[nu * 3 + d] += vn;
                }
                *(float4*)&g_acc4[nu * 4] = make_float4(0.f, 0.f, 0.f, 0.f);
            }
        }
        for (int i = tid; i < TNN * 64; i += 128) {
            int nz = n0 + (i >> 6);
            if (nz < NN) g_agg[nz * 64 + (i & 63)] = 0.f;
        }
        __syncthreads();

        // fused proj: Pa/Pb from h_new
        gemm_t<64>(us, ew1, g_zero64, acc, fc, er, 64);
#pragma unroll
        for (int p = 0; p < 4; p++) {
            int nlo = n0 + 8 * er + 2 * p, nhi = nlo + 1;
#pragma unroll
            for (int j = 0; j < 4; j++) {
                float2 f = u2f(acc[p][j]);
                if (nlo < NN) g_pa[nlo * 64 + 4 * fc + j] = f.x;
                if (nhi < NN) g_pa[nhi * 64 + 4 * fc + j] = f.y;
            }
        }
        gemm_t<64>(us, ew1 + 4096, g_zero64, acc, fc, er, 64);
#pragma unroll
        for (int p = 0; p < 4; p++) {
            int nlo = n0 + 8 * er + 2 * p, nhi = nlo + 1;
#pragma unroll
            for (int j = 0; j < 4; j++) {
                float2 f = u2f(acc[p][j]);
                if (nlo < NN) g_pb[nlo * 64 + 4 * fc + j] = f.x;
                if (nhi < NN) g_pb[nhi * 64 + 4 * fc + j] = f.y;
            }
        }
    }
}

// ---------------- output: [x | h | v] ----------------
__global__ void k_copyout(float* __restrict__ out) {
    int i = blockIdx.x * blockDim.x + threadIdx.x;
    if (i < NN * 3) out[i] = g_x[i];
    if (i < NN * HD) out[NN * 3 + i] = g_h[i];
    if (i < NN * 3) out[NN * 3 + NN * HD + i] = g_v[i];
}

extern "C" void kernel_launch(void* const* d_in, const int* in_sizes, int n_in,
                              void* d_out, int out_size) {
    const float* his = (const float*)d_in[0];
    const float* loc = (const float*)d_in[1];
    const void* edges = d_in[2];
    const float* vel = (const float*)d_in[3];
    const float* eattr = (const float*)d_in[4];
    const float* emb_w = (const float*)d_in[5];
    const float* emb_b = (const float*)d_in[6];
    const float* ew1 = (const float*)d_in[7];
    const float* eb1 = (const float*)d_in[8];
    const float* ew2 = (const float*)d_in[9];
    const float* eb2 = (const float*)d_in[10];
    const float* nw1 = (const float*)d_in[11];
    const float* nb1 = (const float*)d_in[12];
    const float* nw2 = (const float*)d_in[13];
    const float* nb2 = (const float*)d_in[14];
    const float* cw1 = (const float*)d_in[15];
    const float* cb1 = (const float*)d_in[16];
    const float* cw2 = (const float*)d_in[17];
    const float* vw1 = (const float*)d_in[18];
    const float* vb1 = (const float*)d_in[19];
    const float* vw2 = (const float*)d_in[20];
    const float* vb2 = (const float*)d_in[21];

    size_t esm = (size_t)(8192 + 1024 + 256 + 192 + 384) * 4 + 128 * sizeof(int);
    size_t nsm = (size_t)(8192 + 4096 + 4096 + 8192 + 4 * 64 + 64) * 4;
    size_t psm = (size_t)4096 * 4;
    cudaFuncSetAttribute(k_edge, cudaFuncAttributeMaxDynamicSharedMemorySize, (int)esm);
    cudaFuncSetAttribute(k_node, cudaFuncAttributeMaxDynamicSharedMemorySize, (int)nsm);
    cudaFuncSetAttribute(k_proj, cudaFuncAttributeMaxDynamicSharedMemorySize, (int)psm);

    k_detect<<<1, 1>>>(edges);
    k_zhist<<<(NN + 255) / 256, 256>>>();
    k_count<<<(NE + 255) / 256, 256>>>(edges);
    k_scan<<<1, 1024>>>();
    k_permute<<<(NE + 255) / 256, 256>>>(edges, eattr);
    k_init<<<(NN * HD + 255) / 256, 256>>>(his, loc, vel, emb_w, emb_b);
    k_proj<<<157, 128, psm>>>(ew1);
    for (int l = 0; l < NLAYERS; l++) {
        k_edge<<<444, 256, esm>>>(ew1, eb1, ew2, eb2, cw1, cb1, cw2);
        k_node<<<157, 128, nsm>>>(nw1, nb1, nw2, nb2, vw1, vb1, vw2, vb2, ew1);
    }
    k_copyout<<<(NN * HD + 255) / 256, 256>>>((float*)d_out);
}

// round 15
// speedup vs baseline: 1.0069x; 1.0069x over previous
#include <cuda_runtime.h>

#define NN 10000
#define NE 320000
#define HD 64
#define NLAYERS 4
#define TE 128   // edges per tile (edge kernel)
#define TNN 64   // nodes per tile (node/proj kernels)

typedef unsigned long long ull;

// ---------------- scratch state (allocation-free) ----------------
__device__ __align__(16) float g_h[NN * HD];
__device__ __align__(16) float g_agg[NN * HD];
__device__ __align__(16) float g_pa[NN * HD];    // h @ W1[0:64]
__device__ __align__(16) float g_pb[NN * HD];    // h @ W1[64:128]
__device__ __align__(16) float g_acc4[NN * 4];   // [dx,dy,dz,cnt] per node
__device__ float g_x[NN * 3];
__device__ float g_v[NN * 3];
__device__ float g_iv[NN * 3];
__device__ float g_zero64[64];                   // zero-initialized
__device__ int g_edge64;
// sorted-edge scratch
__device__ int g_er[NE];
__device__ int g_ec[NE];
__device__ __align__(8) float g_ea[NE * 2];
__device__ __align__(16) int g_hist[NN];
__device__ __align__(16) int g_cur[NN];

__device__ __forceinline__ float silu_f(float x) {
    return __fdividef(x, 1.0f + __expf(-x));
}

// packed f32x2 helpers
__device__ __forceinline__ ull d2(float x) {
    ull r;
    unsigned u = __float_as_uint(x);
    asm("mov.b64 %0, {%1, %1};" : "=l"(r) : "r"(u));
    return r;
}
__device__ __forceinline__ ull ffma2(ull a, ull b, ull c) {
    ull d;
    asm("fma.rn.f32x2 %0, %1, %2, %3;" : "=l"(d) : "l"(a), "l"(b), "l"(c));
    return d;
}
__device__ __forceinline__ float2 u2f(ull v) {
    unsigned lo, hi;
    asm("mov.b64 {%0, %1}, %2;" : "=r"(lo), "=r"(hi) : "l"(v));
    return make_float2(__uint_as_float(lo), __uint_as_float(hi));
}

// 16B vector reduction (sm_90+)
__device__ __forceinline__ void red4(float* p, float a, float b, float c, float d) {
    asm volatile("red.global.add.v4.f32 [%0], {%1, %2, %3, %4};"
                 :: "l"(p), "f"(a), "f"(b), "f"(c), "f"(d) : "memory");
}

// swizzled staging index (16B-granule xor)
__device__ __forceinline__ int sidx(int k, int e, int RW) {
    return k * RW + ((((e >> 2) ^ ((k >> 2) & 7)) << 2) | (e & 3));
}

__device__ __forceinline__ int edge_idx(const void* edges, long long i) {
    if (g_edge64) return (int)((const long long*)edges)[i];
    return ((const int*)edges)[i];
}

__global__ void k_detect(const void* edges) {
    const int* p = (const int*)edges;
    int is64 = 1;
    for (int i = 1; i < 64; i += 2)
        if (p[i] != 0) is64 = 0;
    g_edge64 = is64;
}

// ---------------- counting sort by row ----------------
__global__ void k_zhist() {
    int i = blockIdx.x * blockDim.x + threadIdx.x;
    if (i < NN) g_hist[i] = 0;
}
__global__ void k_count(const void* __restrict__ edges) {
    int i = blockIdx.x * blockDim.x + threadIdx.x;
    if (i < NE) atomicAdd(&g_hist[edge_idx(edges, i)], 1);
}
__global__ void k_scan() {   // 1 block, 1024 threads, 4 elements/thread
    __shared__ int ws[32];
    __shared__ int carry_s;
    int t = threadIdx.x, lane = t & 31, w = t >> 5;
    if (t == 0) carry_s = 0;
    __syncthreads();
    for (int base = 0; base < NN; base += 4096) {
        int cbase = carry_s;
        int idx = base + 4 * t;
        int4 v = make_int4(0, 0, 0, 0);
        if (idx < NN) v = *(const int4*)&g_hist[idx];   // NN%4==0 -> full vector
        int s = v.x + v.y + v.z + v.w;
        int x = s;
#pragma unroll
        for (int d = 1; d < 32; d <<= 1) {
            int y = __shfl_up_sync(0xffffffffu, x, d);
            if (lane >= d) x += y;
        }
        if (lane == 31) ws[w] = x;
        __syncthreads();
        if (w == 0) {
            int ss = ws[lane];
#pragma unroll
            for (int d = 1; d < 32; d <<= 1) {
                int y = __shfl_up_sync(0xffffffffu, ss, d);
                if (lane >= d) ss += y;
            }
            ws[lane] = ss;
        }
        __syncthreads();
        int excl = cbase + (x - s) + (w ? ws[w - 1] : 0);
        if (idx < NN) {
            int4 o;
            o.x = excl;
            o.y = excl + v.x;
            o.z = o.y + v.y;
            o.w = o.z + v.z;
            *(int4*)&g_cur[idx] = o;
        }
        __syncthreads();
        if (t == 0) carry_s = cbase + ws[31];
        __syncthreads();
    }
}
__global__ void k_permute(const void* __restrict__ edges, const float* __restrict__ ea) {
    int i = blockIdx.x * blockDim.x + threadIdx.x;
    if (i < NE) {
        int r = edge_idx(edges, i);
        int c = edge_idx(edges, (long long)NE + i);
        int pos = atomicAdd(&g_cur[r], 1);
        g_er[pos] = r;
        g_ec[pos] = c;
        float2 v = *(const float2*)&ea[2 * i];
        *(float2*)&g_ea[2 * pos] = v;
    }
}

__global__ void k_init(const float* __restrict__ his, const float* __restrict__ loc,
                       const float* __restrict__ vel, const float* __restrict__ emb_w,
                       const float* __restrict__ emb_b) {
    int idx = blockIdx.x * blockDim.x + threadIdx.x;
    if (idx < NN * HD) {
        int n = idx >> 6, j = idx & 63;
        float a = emb_b[j];
#pragma unroll
        for (int i = 0; i < 4; i++) a = fmaf(his[n * 4 + i], emb_w[i * 64 + j], a);
        g_h[idx] = a;
        g_agg[idx] = 0.f;
    }
    if (idx < NN * 4) g_acc4[idx] = 0.f;
    if (idx < NN * 3) {
        g_x[idx] = loc[idx];
        g_v[idx] = vel[idx];
    }
    if (idx < NN) {
        float vx = vel[idx * 3], vy = vel[idx * 3 + 1], vz = vel[idx * 3 + 2];
        float inv = 1.0f / (sqrtf(vx * vx + vy * vy + vz * vz) + 1e-8f);
        g_iv[idx * 3] = vx * inv;
        g_iv[idx * 3 + 1] = vy * inv;
        g_iv[idx * 3 + 2] = vz * inv;
    }
}

// ---- edge GEMM (R9-proven): warp owns feature octet; W via warp-uniform global LDG ----
template <int RW>
__device__ __forceinline__ void gemm_g(const float* __restrict__ st,
                                       const float* __restrict__ w,
                                       const float* __restrict__ bias,
                                       ull (&acc)[8][2], int wf, int lp, int K) {
#pragma unroll
    for (int j = 0; j < 8; j++) {
        ull bb = d2(bias[8 * wf + j]);
        acc[j][0] = bb;
        acc[j][1] = bb;
    }
    const float* wp = w + 8 * wf;
    for (int k0 = 0; k0 < K; k0 += 4) {
        int s = (k0 >> 2) & 7;
        int o = ((lp ^ s) << 2);
#pragma unroll
        for (int kk = 0; kk < 4; kk++) {
            ulonglong2 a = *(const ulonglong2*)(st + (k0 + kk) * RW + o);
            const float* wr = wp + (k0 + kk) * 64;
            float4 w0 = *(const float4*)(wr);
            float4 w1 = *(const float4*)(wr + 4);
            ull b0 = d2(w0.x), b1 = d2(w0.y), b2 = d2(w0.z), b3 = d2(w0.w);
            ull b4 = d2(w1.x), b5 = d2(w1.y), b6 = d2(w1.z), b7 = d2(w1.w);
            acc[0][0] = ffma2(a.x, b0, acc[0][0]);
            acc[0][1] = ffma2(a.y, b0, acc[0][1]);
            acc[1][0] = ffma2(a.x, b1, acc[1][0]);
            acc[1][1] = ffma2(a.y, b1, acc[1][1]);
            acc[2][0] = ffma2(a.x, b2, acc[2][0]);
            acc[2][1] = ffma2(a.y, b2, acc[2][1]);
            acc[3][0] = ffma2(a.x, b3, acc[3][0]);
            acc[3][1] = ffma2(a.y, b3, acc[3][1]);
            acc[4][0] = ffma2(a.x, b4, acc[4][0]);
            acc[4][1] = ffma2(a.y, b4, acc[4][1]);
            acc[5][0] = ffma2(a.x, b5, acc[5][0]);
            acc[5][1] = ffma2(a.y, b5, acc[5][1]);
            acc[6][0] = ffma2(a.x, b6, acc[6][0]);
            acc[6][1] = ffma2(a.y, b6, acc[6][1]);
            acc[7][0] = ffma2(a.x, b7, acc[7][0]);
            acc[7][1] = ffma2(a.y, b7, acc[7][1]);
        }
    }
}

// silu + feature-major swizzled store of the warp's 8x4 tile
template <int RW>
__device__ __forceinline__ void store_w(float* st, ull (&acc)[8][2], int wf, int lp) {
#pragma unroll
    for (int j = 0; j < 8; j++) {
        int r = 8 * wf + j;
        int s = (r >> 2) & 7;
        float2 f0 = u2f(acc[j][0]), f1 = u2f(acc[j][1]);
        *(float4*)(st + r * RW + ((lp ^ s) << 2)) =
            make_float4(silu_f(f0.x), silu_f(f0.y), silu_f(f1.x), silu_f(f1.y));
    }
}

// ---------------- edge kernel (R9): sorted 128-edge tiles ----------------
__global__ void __launch_bounds__(256, 3)
    k_edge(const float* __restrict__ ew1, const float* __restrict__ eb1,
           const float* __restrict__ ew2, const float* __restrict__ eb2,
           const float* __restrict__ cw1, const float* __restrict__ cb1,
           const float* __restrict__ cw2) {
    extern __shared__ __align__(16) float sm[];
    float* ins = sm;                    // 64*128 = 8192
    float* part = ins + 8192;           // 8*128 gate partials
    float* wtl = part + 1024;           // 64*4: {wr, wa0, wa1, b1} per k
    float* b2s = wtl + 256;             // 64
    float* b3s = b2s + 64;
    float* c2s = b3s + 64;
    float* cds = c2s + 64;              // 3*128
    int* rs = (int*)(cds + 384);        // 128

    const int tid = threadIdx.x;
    const int lane = tid & 31;
    const int wf = tid >> 5;            // feature octet = warp 0..7
    const int lp = lane;                // edge granule (edges 4lp..4lp+3)
    const int e = tid & 127;
    const int which = tid >> 7;         // k-half 0/1 for stage

    if (tid < 64) {
        wtl[tid * 4 + 0] = ew1[128 * 64 + tid];   // radial row
        wtl[tid * 4 + 1] = ew1[129 * 64 + tid];   // eattr row 0
        wtl[tid * 4 + 2] = ew1[130 * 64 + tid];   // eattr row 1
        wtl[tid * 4 + 3] = eb1[tid];
        b2s[tid] = eb2[tid];
        b3s[tid] = cb1[tid];
        c2s[tid] = cw2[tid];
    }

    const int ntile = NE / TE;
    for (int t = blockIdx.x; t < ntile; t += gridDim.x) {
        __syncthreads();
        int e0 = t * TE;
        int r = g_er[e0 + e];
        int c = g_ec[e0 + e];
        if (which == 0) rs[e] = r;   // consumed only after later barriers

        // stage t1 = silu(Pa[row] + Pb[col] + rad*wr + ea@we + b1); 2 threads/edge
        float dx = g_x[r * 3] - g_x[c * 3];
        float dy = g_x[r * 3 + 1] - g_x[c * 3 + 1];
        float dz = g_x[r * 3 + 2] - g_x[c * 3 + 2];
        float rad = dx * dx + dy * dy + dz * dz;
        float2 ea = *(const float2*)&g_ea[(e0 + e) * 2];
        if (which == 0) {
            cds[e] = dx;
            cds[128 + e] = dy;
            cds[256 + e] = dz;
        }
        {
            const float4* pa = (const float4*)&g_pa[r * 64 + which * 32];
            const float4* pb = (const float4*)&g_pb[c * 64 + which * 32];
#pragma unroll
            for (int q = 0; q < 8; q++) {
                int k = which * 32 + 4 * q;
                float4 va = pa[q], vb = pb[q];
                float4 t0 = *(const float4*)&wtl[(k + 0) * 4];
                float4 t1 = *(const float4*)&wtl[(k + 1) * 4];
                float4 t2 = *(const float4*)&wtl[(k + 2) * 4];
                float4 t3 = *(const float4*)&wtl[(k + 3) * 4];
                float v0 = va.x + vb.x + rad * t0.x + ea.x * t0.y + ea.y * t0.z + t0.w;
                float v1 = va.y + vb.y + rad * t1.x + ea.x * t1.y + ea.y * t1.z + t1.w;
                float v2 = va.z + vb.z + rad * t2.x + ea.x * t2.y + ea.y * t2.z + t2.w;
                float v3 = va.w + vb.w + rad * t3.x + ea.x * t3.y + ea.y * t3.z + t3.w;
                ins[sidx(k + 0, e, 128)] = silu_f(v0);
                ins[sidx(k + 1, e, 128)] = silu_f(v1);
                ins[sidx(k + 2, e, 128)] = silu_f(v2);
                ins[sidx(k + 3, e, 128)] = silu_f(v3);
            }
        }
        __syncthreads();

        ull acc[8][2];
        // GEMM2: t1@[64,64] + b2, silu -> ef (in-place)
        gemm_g<128>(ins, ew2, b2s, acc, wf, lp, 64);
        __syncthreads();
        store_w<128>(ins, acc, wf, lp);
        __syncthreads();

        // GEMM3: ef@cw1 + b3, silu, dot cw2 -> per-warp gate partials
        gemm_g<128>(ins, cw1, b3s, acc, wf, lp, 64);
        {
            float g0 = 0.f, g1 = 0.f, g2 = 0.f, g3 = 0.f;
#pragma unroll
            for (int j = 0; j < 8; j++) {
                float cj = c2s[8 * wf + j];
                float2 f0 = u2f(acc[j][0]), f1 = u2f(acc[j][1]);
                g0 = fmaf(silu_f(f0.x), cj, g0);
                g1 = fmaf(silu_f(f0.y), cj, g1);
                g2 = fmaf(silu_f(f1.x), cj, g2);
                g3 = fmaf(silu_f(f1.y), cj, g3);
            }
            *(float4*)(part + wf * 128 + 4 * lp) = make_float4(g0, g1, g2, g3);
        }
        __syncthreads();

        // scatter with run-length pre-reduction (edges sorted by row)
        {
            int oct = tid & 15;        // edge octet (8 edges)
            int chunk = tid >> 4;      // feature 16B chunk 0..15
            int rprev = rs[oct * 8];
            float4 av = make_float4(0.f, 0.f, 0.f, 0.f);
#pragma unroll
            for (int j = 0; j < 8; j++) {
                int ee = oct * 8 + j;
                int rr = rs[ee];
                float v0 = ins[sidx(4 * chunk + 0, ee, 128)];
                float v1 = ins[sidx(4 * chunk + 1, ee, 128)];
                float v2 = ins[sidx(4 * chunk + 2, ee, 128)];
                float v3 = ins[sidx(4 * chunk + 3, ee, 128)];
                if (rr != rprev) {
                    red4(&g_agg[rprev * 64 + chunk * 4], av.x, av.y, av.z, av.w);
                    av = make_float4(v0, v1, v2, v3);
                    rprev = rr;
                } else {
                    av.x += v0;
                    av.y += v1;
                    av.z += v2;
                    av.w += v3;
                }
            }
            red4(&g_agg[rprev * 64 + chunk * 4], av.x, av.y, av.z, av.w);
        }
        if (tid < 16) {
            int oct = tid;
            int rprev = rs[oct * 8];
            float4 a4 = make_float4(0.f, 0.f, 0.f, 0.f);
#pragma unroll
            for (int j = 0; j < 8; j++) {
                int ee = oct * 8 + j;
                int rr = rs[ee];
                float gg = 0.f;
#pragma unroll
                for (int w8 = 0; w8 < 8; w8++) gg += part[w8 * 128 + ee];
                float gx = cds[ee] * gg, gy = cds[128 + ee] * gg, gz = cds[256 + ee] * gg;
                if (rr != rprev) {
                    red4(&g_acc4[rprev * 4], a4.x, a4.y, a4.z, a4.w);
                    a4 = make_float4(gx, gy, gz, 1.0f);
                    rprev = rr;
                } else {
                    a4.x += gx;
                    a4.y += gy;
                    a4.z += gz;
                    a4.w += 1.0f;
                }
            }
            red4(&g_acc4[rprev * 4], a4.x, a4.y, a4.z, a4.w);
        }
    }
}

// ======== 4-pair GEMM micro-kernel (node/proj; RW=64) ========
template <int RW>
__device__ __forceinline__ void gemm_t(const float* __restrict__ st,
                                       const float* __restrict__ w,
                                       const float* __restrict__ bias,
                                       ull (&acc)[4][4], int fc, int er, int K) {
#pragma unroll
    for (int j = 0; j < 4; j++) {
        ull bb = d2(bias[4 * fc + j]);
#pragma unroll
        for (int p = 0; p < 4; p++) acc[p][j] = bb;
    }
    const int eg0 = 2 * er, eg1 = 2 * er + 1;
#pragma unroll 2
    for (int k0 = 0; k0 < K; k0 += 4) {
        int ss = (k0 >> 2) & 7;
        int o0 = ((eg0 ^ ss) << 2), o1 = ((eg1 ^ ss) << 2);
#pragma unroll
        for (int kk = 0; kk < 4; kk++) {
            const float* rp = st + (k0 + kk) * RW;
            ulonglong2 aA = *(const ulonglong2*)(rp + o0);
            ulonglong2 aB = *(const ulonglong2*)(rp + o1);
            float4 wv = *(const float4*)(w + (k0 + kk) * 64 + 4 * fc);
            ull b0 = d2(wv.x), b1 = d2(wv.y), b2 = d2(wv.z), b3 = d2(wv.w);
            acc[0][0] = ffma2(aA.x, b0, acc[0][0]);
            acc[1][0] = ffma2(aA.y, b0, acc[1][0]);
            acc[2][0] = ffma2(aB.x, b0, acc[2][0]);
            acc[3][0] = ffma2(aB.y, b0, acc[3][0]);
            acc[0][1] = ffma2(aA.x, b1, acc[0][1]);
            acc[1][1] = ffma2(aA.y, b1, acc[1][1]);
            acc[2][1] = ffma2(aB.x, b1, acc[2][1]);
            acc[3][1] = ffma2(aB.y, b1, acc[3][1]);
            acc[0][2] = ffma2(aA.x, b2, acc[0][2]);
            acc[1][2] = ffma2(aA.y, b2, acc[1][2]);
            acc[2][2] = ffma2(aB.x, b2, acc[2][2]);
            acc[3][2] = ffma2(aB.y, b2, acc[3][2]);
            acc[0][3] = ffma2(aA.x, b3, acc[0][3]);
            acc[1][3] = ffma2(aA.y, b3, acc[1][3]);
            acc[2][3] = ffma2(aB.x, b3, acc[2][3]);
            acc[3][3] = ffma2(aB.y, b3, acc[3][3]);
        }
    }
}

template <int RW>
__device__ __forceinline__ void store_silu_t4(float* st, ull (&acc)[4][4], int fc, int er) {
    int ss = fc & 7;
    int o0 = (((2 * er) ^ ss) << 2), o1 = (((2 * er + 1) ^ ss) << 2);
#pragma unroll
    for (int j = 0; j < 4; j++) {
        int r = 4 * fc + j;
        float2 f0 = u2f(acc[0][j]), f1 = u2f(acc[1][j]);
        float2 f2 = u2f(acc[2][j]), f3 = u2f(acc[3][j]);
        float4 v0 = make_float4(silu_f(f0.x), silu_f(f0.y), silu_f(f1.x), silu_f(f1.y));
        float4 v1 = make_float4(silu_f(f2.x), silu_f(f2.y), silu_f(f3.x), silu_f(f3.y));
        *(float4*)(st + r * RW + o0) = v0;
        *(float4*)(st + r * RW + o1) = v1;
    }
}

// ---------------- proj kernel (initial only) ----------------
__global__ void __launch_bounds__(128, 2)
    k_proj(const float* __restrict__ ew1) {
    extern __shared__ __align__(16) float sm[];
    float* us = sm;             // 64*64

    const int tid = threadIdx.x;
    const int fc = tid & 15;
    const int er = tid >> 4;
    const int e = tid & 63;
    const int half = tid >> 6;

    const int ntile = (NN + TNN - 1) / TNN;
    for (int t = blockIdx.x; t < ntile; t += gridDim.x) {
        __syncthreads();
        int n0 = t * TNN;
        int n = n0 + e;
#pragma unroll
        for (int q = 0; q < 8; q++) {
            int kq = half * 8 + q;
            float4 hv = make_float4(0, 0, 0, 0);
            if (n < NN) hv = *(const float4*)&g_h[n * 64 + 4 * kq];
            us[sidx(4 * kq + 0, e, 64)] = hv.x;
            us[sidx(4 * kq + 1, e, 64)] = hv.y;
            us[sidx(4 * kq + 2, e, 64)] = hv.z;
            us[sidx(4 * kq + 3, e, 64)] = hv.w;
        }
        __syncthreads();

        ull acc[4][4];
        gemm_t<64>(us, ew1, g_zero64, acc, fc, er, 64);
#pragma unroll
        for (int p = 0; p < 4; p++) {
            int nlo = n0 + 8 * er + 2 * p, nhi = nlo + 1;
#pragma unroll
            for (int j = 0; j < 4; j++) {
                float2 f = u2f(acc[p][j]);
                if (nlo < NN) g_pa[nlo * 64 + 4 * fc + j] = f.x;
                if (nhi < NN) g_pa[nhi * 64 + 4 * fc + j] = f.y;
            }
        }
        gemm_t<64>(us, ew1 + 4096, g_zero64, acc, fc, er, 64);
#pragma unroll
        for (int p = 0; p < 4; p++) {
            int nlo = n0 + 8 * er + 2 * p, nhi = nlo + 1;
#pragma unroll
            for (int j = 0; j < 4; j++) {
                float2 f = u2f(acc[p][j]);
                if (nlo < NN) g_pb[nlo * 64 + 4 * fc + j] = f.x;
                if (nhi < NN) g_pb[nhi * 64 + 4 * fc + j] = f.y;
            }
        }
    }
}

// ---------------- node kernel (R9 + fused agg-zero): MLPs + update + proj ----------------
__global__ void __launch_bounds__(128, 2)
    k_node(const float* __restrict__ nw1, const float* __restrict__ nb1,
           const float* __restrict__ nw2, const float* __restrict__ nb2,
           const float* __restrict__ vw1, const float* __restrict__ vb1,
           const float* __restrict__ vw2, const float* __restrict__ vb2,
           const float* __restrict__ ew1) {
    extern __shared__ __align__(16) float sm[];
    float* wn1 = sm;
    float* wn2 = wn1 + 8192;
    float* wv1 = wn2 + 4096;
    float* us = wv1 + 4096;
    float* nb1s = us + 8192;
    float* nb2s = nb1s + 64;
    float* vb1s = nb2s + 64;
    float* vw2s = vb1s + 64;
    float* phis = vw2s + 64;

    const int tid = threadIdx.x;
    const int fc = tid & 15;
    const int er = tid >> 4;

    for (int i = tid; i < 2048; i += 128) ((float4*)wn1)[i] = ((const float4*)nw1)[i];
    for (int i = tid; i < 1024; i += 128) {
        ((float4*)wn2)[i] = ((const float4*)nw2)[i];
        ((float4*)wv1)[i] = ((const float4*)vw1)[i];
    }
    if (tid < 64) {
        nb1s[tid] = nb1[tid];
        nb2s[tid] = nb2[tid];
        vb1s[tid] = vb1[tid];
        vw2s[tid] = vw2[tid];
    }
    const float vb2v = vb2[0];

    const int e = tid & 63;
    const int half = tid >> 6;
    const int ntile = (NN + TNN - 1) / TNN;
    for (int t = blockIdx.x; t < ntile; t += gridDim.x) {
        __syncthreads();
        int n0 = t * TNN;
        int n = n0 + e;
#pragma unroll
        for (int q = 0; q < 8; q++) {
            int kq = half * 8 + q;
            float4 hv = make_float4(0, 0, 0, 0), av = make_float4(0, 0, 0, 0);
            if (n < NN) {
                hv = *(const float4*)&g_h[n * 64 + 4 * kq];
                av = *(const float4*)&g_agg[n * 64 + 4 * kq];
                // fused zero: this agg slot is not read again until next
                // layer's edge red4 accumulates into it
                *(float4*)&g_agg[n * 64 + 4 * kq] = make_float4(0.f, 0.f, 0.f, 0.f);
            }
            us[sidx(4 * kq + 0, e, 64)] = hv.x;
            us[sidx(4 * kq + 1, e, 64)] = hv.y;
            us[sidx(4 * kq + 2, e, 64)] = hv.z;
            us[sidx(4 * kq + 3, e, 64)] = hv.w;
            us[sidx(64 + 4 * kq + 0, e, 64)] = av.x;
            us[sidx(64 + 4 * kq + 1, e, 64)] = av.y;
            us[sidx(64 + 4 * kq + 2, e, 64)] = av.z;
            us[sidx(64 + 4 * kq + 3, e, 64)] = av.w;
        }
        __syncthreads();

        ull acc[4][4];
        // vel MLP
        gemm_t<64>(us, wv1, vb1s, acc, fc, er, 64);
        {
            float gv[8] = {0.f, 0.f, 0.f, 0.f, 0.f, 0.f, 0.f, 0.f};
#pragma unroll
            for (int p = 0; p < 4; p++)
#pragma unroll
                for (int j = 0; j < 4; j++) {
                    float2 f = u2f(acc[p][j]);
                    float cj = vw2s[4 * fc + j];
                    gv[2 * p] = fmaf(silu_f(f.x), cj, gv[2 * p]);
                    gv[2 * p + 1] = fmaf(silu_f(f.y), cj, gv[2 * p + 1]);
                }
#pragma unroll
            for (int m = 1; m < 16; m <<= 1)
#pragma unroll
                for (int i = 0; i < 8; i++)
                    gv[i] += __shfl_xor_sync(0xffffffffu, gv[i], m);
            if (fc == 0)
#pragma unroll
                for (int i = 0; i < 8; i++) phis[8 * er + i] = gv[i] + vb2v;
        }

        // node GEMM1
        gemm_t<64>(us, wn1, nb1s, acc, fc, er, 128);
        __syncthreads();
        store_silu_t4<64>(us + 64 * 64, acc, fc, er);
        __syncthreads();

        // node GEMM2 -> hn; h += hn; restage h_new
        gemm_t<64>(us + 64 * 64, wn2, nb2s, acc, fc, er, 64);
#pragma unroll
        for (int p = 0; p < 4; p++) {
            int nlo = n0 + 8 * er + 2 * p, nhi = nlo + 1;
#pragma unroll
            for (int j = 0; j < 4; j++) {
                float2 f = u2f(acc[p][j]);
                if (nlo < NN) {
                    float hx = g_h[nlo * 64 + 4 * fc + j] + f.x;
                    g_h[nlo * 64 + 4 * fc + j] = hx;
                    us[sidx(4 * fc + j, 8 * er + 2 * p, 64)] = hx;
                }
                if (nhi < NN) {
                    float hx = g_h[nhi * 64 + 4 * fc + j] + f.y;
                    g_h[nhi * 64 + 4 * fc + j] = hx;
                    us[sidx(4 * fc + j, 8 * er + 2 * p + 1, 64)] = hx;
                }
            }
        }

        // per-node coord/vel update
        if (tid < TNN) {
            int nu = n0 + tid;
            if (nu < NN) {
                float cnt = g_acc4[nu * 4 + 3];
                float inv = 1.0f / fmaxf(cnt, 1.0f);
                float phi = phis[tid];
#pragma unroll
                for (int d = 0; d < 3; d++) {
                    float a = g_acc4[nu * 4 + d] * inv;
                    float vn = g_v[nu * 3 + d] + a + phi * g_iv[nu * 3 + d];
                    g_v[nu * 3 + d] = vn;
                    g_x[nu * 3 + d] += vn;
                }
                *(float4*)&g_acc4[nu * 4] = make_float4(0.f, 0.f, 0.f, 0.f);
            }
        }
        __syncthreads();

        // fused proj: Pa/Pb from h_new
        gemm_t<64>(us, ew1, g_zero64, acc, fc, er, 64);
#pragma unroll
        for (int p = 0; p < 4; p++) {
            int nlo = n0 + 8 * er + 2 * p, nhi = nlo + 1;
#pragma unroll
            for (int j = 0; j < 4; j++) {
                float2 f = u2f(acc[p][j]);
                if (nlo < NN) g_pa[nlo * 64 + 4 * fc + j] = f.x;
                if (nhi < NN) g_pa[nhi * 64 + 4 * fc + j] = f.y;
            }
        }
        gemm_t<64>(us, ew1 + 4096, g_zero64, acc, fc, er, 64);
#pragma unroll
        for (int p = 0; p < 4; p++) {
            int nlo = n0 + 8 * er + 2 * p, nhi = nlo + 1;
#pragma unroll
            for (int j = 0; j < 4; j++) {
                float2 f = u2f(acc[p][j]);
                if (nlo < NN) g_pb[nlo * 64 + 4 * fc + j] = f.x;
                if (nhi < NN) g_pb[nhi * 64 + 4 * fc + j] = f.y;
            }
        }
    }
}

// ---------------- output: [x | h | v] ----------------
__global__ void k_copyout(float* __restrict__ out) {
    int i = blockIdx.x * blockDim.x + threadIdx.x;
    if (i < NN * 3) out[i] = g_x[i];
    if (i < NN * HD) out[NN * 3 + i] = g_h[i];
    if (i < NN * 3) out[NN * 3 + NN * HD + i] = g_v[i];
}

extern "C" void kernel_launch(void* const* d_in, const int* in_sizes, int n_in,
                              void* d_out, int out_size) {
    const float* his = (const float*)d_in[0];
    const float* loc = (const float*)d_in[1];
    const void* edges = d_in[2];
    const float* vel = (const float*)d_in[3];
    const float* eattr = (const float*)d_in[4];
    const float* emb_w = (const float*)d_in[5];
    const float* emb_b = (const float*)d_in[6];
    const float* ew1 = (const float*)d_in[7];
    const float* eb1 = (const float*)d_in[8];
    const float* ew2 = (const float*)d_in[9];
    const float* eb2 = (const float*)d_in[10];
    const float* nw1 = (const float*)d_in[11];
    const float* nb1 = (const float*)d_in[12];
    const float* nw2 = (const float*)d_in[13];
    const float* nb2 = (const float*)d_in[14];
    const float* cw1 = (const float*)d_in[15];
    const float* cb1 = (const float*)d_in[16];
    const float* cw2 = (const float*)d_in[17];
    const float* vw1 = (const float*)d_in[18];
    const float* vb1 = (const float*)d_in[19];
    const float* vw2 = (const float*)d_in[20];
    const float* vb2 = (const float*)d_in[21];

    size_t esm = (size_t)(8192 + 1024 + 256 + 192 + 384) * 4 + 128 * sizeof(int);
    size_t nsm = (size_t)(8192 + 4096 + 4096 + 8192 + 4 * 64 + 64) * 4;
    size_t psm = (size_t)4096 * 4;
    cudaFuncSetAttribute(k_edge, cudaFuncAttributeMaxDynamicSharedMemorySize, (int)esm);
    cudaFuncSetAttribute(k_node, cudaFuncAttributeMaxDynamicSharedMemorySize, (int)nsm);
    cudaFuncSetAttribute(k_proj, cudaFuncAttributeMaxDynamicSharedMemorySize, (int)psm);

    k_detect<<<1, 1>>>(edges);
    k_zhist<<<(NN + 255) / 256, 256>>>();
    k_count<<<(NE + 255) / 256, 256>>>(edges);
    k_scan<<<1, 1024>>>();
    k_permute<<<(NE + 255) / 256, 256>>>(edges, eattr);
    k_init<<<(NN * HD + 255) / 256, 256>>>(his, loc, vel, emb_w, emb_b);
    k_proj<<<157, 128, psm>>>(ew1);
    for (int l = 0; l < NLAYERS; l++) {
        k_edge<<<444, 256, esm>>>(ew1, eb1, ew2, eb2, cw1, cb1, cw2);
        k_node<<<157, 128, nsm>>>(nw1, nb1, nw2, nb2, vw1, vb1, vw2, vb2, ew1);
    }
    k_copyout<<<(NN * HD + 255) / 256, 256>>>((float*)d_out);
}

// round 16
// speedup vs baseline: 1.0375x; 1.0304x over previous
#include <cuda_runtime.h>

#define NN 10000
#define NE 320000
#define HD 64
#define NLAYERS 4
#define TE 128   // edges per tile (edge kernel)
#define TNN 64   // nodes per tile (node/proj kernels)

typedef unsigned long long ull;

// ---------------- scratch state (allocation-free) ----------------
__device__ __align__(16) float g_h[NN * HD];
__device__ __align__(16) float g_agg[NN * HD];
__device__ __align__(16) float g_pa[NN * HD];    // h @ W1[0:64]
__device__ __align__(16) float g_pb[NN * HD];    // h @ W1[64:128]
__device__ __align__(16) float g_acc4[NN * 4];   // [dx,dy,dz,cnt] per node
__device__ float g_x[NN * 3];
__device__ float g_v[NN * 3];
__device__ float g_iv[NN * 3];
__device__ float g_zero64[64];                   // zero-initialized
__device__ int g_edge64;
// sorted-edge scratch
__device__ int g_er[NE];
__device__ int g_ec[NE];
__device__ __align__(8) float g_ea[NE * 2];
__device__ __align__(16) int g_hist[NN];
__device__ __align__(16) int g_cur[NN];

__device__ __forceinline__ float silu_f(float x) {
    return __fdividef(x, 1.0f + __expf(-x));
}

// packed f32x2 helpers
__device__ __forceinline__ ull d2(float x) {
    ull r;
    unsigned u = __float_as_uint(x);
    asm("mov.b64 %0, {%1, %1};" : "=l"(r) : "r"(u));
    return r;
}
__device__ __forceinline__ ull ffma2(ull a, ull b, ull c) {
    ull d;
    asm("fma.rn.f32x2 %0, %1, %2, %3;" : "=l"(d) : "l"(a), "l"(b), "l"(c));
    return d;
}
__device__ __forceinline__ float2 u2f(ull v) {
    unsigned lo, hi;
    asm("mov.b64 {%0, %1}, %2;" : "=r"(lo), "=r"(hi) : "l"(v));
    return make_float2(__uint_as_float(lo), __uint_as_float(hi));
}

// 16B vector reduction (sm_90+)
__device__ __forceinline__ void red4(float* p, float a, float b, float c, float d) {
    asm volatile("red.global.add.v4.f32 [%0], {%1, %2, %3, %4};"
                 :: "l"(p), "f"(a), "f"(b), "f"(c), "f"(d) : "memory");
}

// swizzled staging index (16B-granule xor)
__device__ __forceinline__ int sidx(int k, int e, int RW) {
    return k * RW + ((((e >> 2) ^ ((k >> 2) & 7)) << 2) | (e & 3));
}

__device__ __forceinline__ int edge_idx(const void* edges, long long i) {
    if (g_edge64) return (int)((const long long*)edges)[i];
    return ((const int*)edges)[i];
}

__global__ void k_detect(const void* edges) {
    const int* p = (const int*)edges;
    int is64 = 1;
    for (int i = 1; i < 64; i += 2)
        if (p[i] != 0) is64 = 0;
    g_edge64 = is64;
}

// ---------------- counting sort by row ----------------
__global__ void k_zhist() {
    int i = blockIdx.x * blockDim.x + threadIdx.x;
    if (i < NN) g_hist[i] = 0;
}
__global__ void k_count(const void* __restrict__ edges) {
    int i = blockIdx.x * blockDim.x + threadIdx.x;
    if (i < NE) atomicAdd(&g_hist[edge_idx(edges, i)], 1);
}
__global__ void k_scan() {   // 1 block, 1024 threads, 4 elements/thread (measured 2x faster)
    __shared__ int ws[32];
    __shared__ int carry_s;
    int t = threadIdx.x, lane = t & 31, w = t >> 5;
    if (t == 0) carry_s = 0;
    __syncthreads();
    for (int base = 0; base < NN; base += 4096) {
        int cbase = carry_s;
        int idx = base + 4 * t;
        int4 v = make_int4(0, 0, 0, 0);
        if (idx < NN) v = *(const int4*)&g_hist[idx];   // NN%4==0 -> full vector
        int s = v.x + v.y + v.z + v.w;
        int x = s;
#pragma unroll
        for (int d = 1; d < 32; d <<= 1) {
            int y = __shfl_up_sync(0xffffffffu, x, d);
            if (lane >= d) x += y;
        }
        if (lane == 31) ws[w] = x;
        __syncthreads();
        if (w == 0) {
            int ss = ws[lane];
#pragma unroll
            for (int d = 1; d < 32; d <<= 1) {
                int y = __shfl_up_sync(0xffffffffu, ss, d);
                if (lane >= d) ss += y;
            }
            ws[lane] = ss;
        }
        __syncthreads();
        int excl = cbase + (x - s) + (w ? ws[w - 1] : 0);
        if (idx < NN) {
            int4 o;
            o.x = excl;
            o.y = excl + v.x;
            o.z = o.y + v.y;
            o.w = o.z + v.z;
            *(int4*)&g_cur[idx] = o;
        }
        __syncthreads();
        if (t == 0) carry_s = cbase + ws[31];
        __syncthreads();
    }
}
__global__ void k_permute(const void* __restrict__ edges, const float* __restrict__ ea) {
    int i = blockIdx.x * blockDim.x + threadIdx.x;
    if (i < NE) {
        int r = edge_idx(edges, i);
        int c = edge_idx(edges, (long long)NE + i);
        int pos = atomicAdd(&g_cur[r], 1);
        g_er[pos] = r;
        g_ec[pos] = c;
        float2 v = *(const float2*)&ea[2 * i];
        *(float2*)&g_ea[2 * pos] = v;
    }
}

__global__ void k_init(const float* __restrict__ his, const float* __restrict__ loc,
                       const float* __restrict__ vel, const float* __restrict__ emb_w,
                       const float* __restrict__ emb_b) {
    int idx = blockIdx.x * blockDim.x + threadIdx.x;
    if (idx < NN * HD) {
        int n = idx >> 6, j = idx & 63;
        float a = emb_b[j];
#pragma unroll
        for (int i = 0; i < 4; i++) a = fmaf(his[n * 4 + i], emb_w[i * 64 + j], a);
        g_h[idx] = a;
        g_agg[idx] = 0.f;
    }
    if (idx < NN * 4) g_acc4[idx] = 0.f;
    if (idx < NN * 3) {
        g_x[idx] = loc[idx];
        g_v[idx] = vel[idx];
    }
    if (idx < NN) {
        float vx = vel[idx * 3], vy = vel[idx * 3 + 1], vz = vel[idx * 3 + 2];
        float inv = 1.0f / (sqrtf(vx * vx + vy * vy + vz * vz) + 1e-8f);
        g_iv[idx * 3] = vx * inv;
        g_iv[idx * 3 + 1] = vy * inv;
        g_iv[idx * 3 + 2] = vz * inv;
    }
}

// ---- edge GEMM (R9-proven): warp owns feature octet; W via warp-uniform global LDG ----
template <int RW>
__device__ __forceinline__ void gemm_g(const float* __restrict__ st,
                                       const float* __restrict__ w,
                                       const float* __restrict__ bias,
                                       ull (&acc)[8][2], int wf, int lp, int K) {
#pragma unroll
    for (int j = 0; j < 8; j++) {
        ull bb = d2(bias[8 * wf + j]);
        acc[j][0] = bb;
        acc[j][1] = bb;
    }
    const float* wp = w + 8 * wf;
    for (int k0 = 0; k0 < K; k0 += 4) {
        int s = (k0 >> 2) & 7;
        int o = ((lp ^ s) << 2);
#pragma unroll
        for (int kk = 0; kk < 4; kk++) {
            ulonglong2 a = *(const ulonglong2*)(st + (k0 + kk) * RW + o);
            const float* wr = wp + (k0 + kk) * 64;
            float4 w0 = *(const float4*)(wr);
            float4 w1 = *(const float4*)(wr + 4);
            ull b0 = d2(w0.x), b1 = d2(w0.y), b2 = d2(w0.z), b3 = d2(w0.w);
            ull b4 = d2(w1.x), b5 = d2(w1.y), b6 = d2(w1.z), b7 = d2(w1.w);
            acc[0][0] = ffma2(a.x, b0, acc[0][0]);
            acc[0][1] = ffma2(a.y, b0, acc[0][1]);
            acc[1][0] = ffma2(a.x, b1, acc[1][0]);
            acc[1][1] = ffma2(a.y, b1, acc[1][1]);
            acc[2][0] = ffma2(a.x, b2, acc[2][0]);
            acc[2][1] = ffma2(a.y, b2, acc[2][1]);
            acc[3][0] = ffma2(a.x, b3, acc[3][0]);
            acc[3][1] = ffma2(a.y, b3, acc[3][1]);
            acc[4][0] = ffma2(a.x, b4, acc[4][0]);
            acc[4][1] = ffma2(a.y, b4, acc[4][1]);
            acc[5][0] = ffma2(a.x, b5, acc[5][0]);
            acc[5][1] = ffma2(a.y, b5, acc[5][1]);
            acc[6][0] = ffma2(a.x, b6, acc[6][0]);
            acc[6][1] = ffma2(a.y, b6, acc[6][1]);
            acc[7][0] = ffma2(a.x, b7, acc[7][0]);
            acc[7][1] = ffma2(a.y, b7, acc[7][1]);
        }
    }
}

// silu + feature-major swizzled store of the warp's 8x4 tile
template <int RW>
__device__ __forceinline__ void store_w(float* st, ull (&acc)[8][2], int wf, int lp) {
#pragma unroll
    for (int j = 0; j < 8; j++) {
        int r = 8 * wf + j;
        int s = (r >> 2) & 7;
        float2 f0 = u2f(acc[j][0]), f1 = u2f(acc[j][1]);
        *(float4*)(st + r * RW + ((lp ^ s) << 2)) =
            make_float4(silu_f(f0.x), silu_f(f0.y), silu_f(f1.x), silu_f(f1.y));
    }
}

// ---------------- edge kernel (R9 verbatim): sorted 128-edge tiles ----------------
__global__ void __launch_bounds__(256, 3)
    k_edge(const float* __restrict__ ew1, const float* __restrict__ eb1,
           const float* __restrict__ ew2, const float* __restrict__ eb2,
           const float* __restrict__ cw1, const float* __restrict__ cb1,
           const float* __restrict__ cw2) {
    extern __shared__ __align__(16) float sm[];
    float* ins = sm;                    // 64*128 = 8192
    float* part = ins + 8192;           // 8*128 gate partials
    float* wtl = part + 1024;           // 64*4: {wr, wa0, wa1, b1} per k
    float* b2s = wtl + 256;             // 64
    float* b3s = b2s + 64;
    float* c2s = b3s + 64;
    float* cds = c2s + 64;              // 3*128
    int* rs = (int*)(cds + 384);        // 128

    const int tid = threadIdx.x;
    const int lane = tid & 31;
    const int wf = tid >> 5;            // feature octet = warp 0..7
    const int lp = lane;                // edge granule (edges 4lp..4lp+3)
    const int e = tid & 127;
    const int which = tid >> 7;         // k-half 0/1 for stage

    if (tid < 64) {
        wtl[tid * 4 + 0] = ew1[128 * 64 + tid];   // radial row
        wtl[tid * 4 + 1] = ew1[129 * 64 + tid];   // eattr row 0
        wtl[tid * 4 + 2] = ew1[130 * 64 + tid];   // eattr row 1
        wtl[tid * 4 + 3] = eb1[tid];
        b2s[tid] = eb2[tid];
        b3s[tid] = cb1[tid];
        c2s[tid] = cw2[tid];
    }

    const int ntile = NE / TE;
    for (int t = blockIdx.x; t < ntile; t += gridDim.x) {
        __syncthreads();
        int e0 = t * TE;
        int r = g_er[e0 + e];
        int c = g_ec[e0 + e];
        if (which == 0) rs[e] = r;
        __syncthreads();

        // stage t1 = silu(Pa[row] + Pb[col] + rad*wr + ea@we + b1); 2 threads/edge
        float dx = g_x[r * 3] - g_x[c * 3];
        float dy = g_x[r * 3 + 1] - g_x[c * 3 + 1];
        float dz = g_x[r * 3 + 2] - g_x[c * 3 + 2];
        float rad = dx * dx + dy * dy + dz * dz;
        float2 ea = *(const float2*)&g_ea[(e0 + e) * 2];
        if (which == 0) {
            cds[e] = dx;
            cds[128 + e] = dy;
            cds[256 + e] = dz;
        }
        {
            const float4* pa = (const float4*)&g_pa[r * 64 + which * 32];
            const float4* pb = (const float4*)&g_pb[c * 64 + which * 32];
#pragma unroll
            for (int q = 0; q < 8; q++) {
                int k = which * 32 + 4 * q;
                float4 va = pa[q], vb = pb[q];
                float4 t0 = *(const float4*)&wtl[(k + 0) * 4];
                float4 t1 = *(const float4*)&wtl[(k + 1) * 4];
                float4 t2 = *(const float4*)&wtl[(k + 2) * 4];
                float4 t3 = *(const float4*)&wtl[(k + 3) * 4];
                float v0 = va.x + vb.x + rad * t0.x + ea.x * t0.y + ea.y * t0.z + t0.w;
                float v1 = va.y + vb.y + rad * t1.x + ea.x * t1.y + ea.y * t1.z + t1.w;
                float v2 = va.z + vb.z + rad * t2.x + ea.x * t2.y + ea.y * t2.z + t2.w;
                float v3 = va.w + vb.w + rad * t3.x + ea.x * t3.y + ea.y * t3.z + t3.w;
                ins[sidx(k + 0, e, 128)] = silu_f(v0);
                ins[sidx(k + 1, e, 128)] = silu_f(v1);
                ins[sidx(k + 2, e, 128)] = silu_f(v2);
                ins[sidx(k + 3, e, 128)] = silu_f(v3);
            }
        }
        __syncthreads();

        ull acc[8][2];
        // GEMM2: t1@[64,64] + b2, silu -> ef (in-place)
        gemm_g<128>(ins, ew2, b2s, acc, wf, lp, 64);
        __syncthreads();
        store_w<128>(ins, acc, wf, lp);
        __syncthreads();

        // GEMM3: ef@cw1 + b3, silu, dot cw2 -> per-warp gate partials
        gemm_g<128>(ins, cw1, b3s, acc, wf, lp, 64);
        {
            float g0 = 0.f, g1 = 0.f, g2 = 0.f, g3 = 0.f;
#pragma unroll
            for (int j = 0; j < 8; j++) {
                float cj = c2s[8 * wf + j];
                float2 f0 = u2f(acc[j][0]), f1 = u2f(acc[j][1]);
                g0 = fmaf(silu_f(f0.x), cj, g0);
                g1 = fmaf(silu_f(f0.y), cj, g1);
                g2 = fmaf(silu_f(f1.x), cj, g2);
                g3 = fmaf(silu_f(f1.y), cj, g3);
            }
            *(float4*)(part + wf * 128 + 4 * lp) = make_float4(g0, g1, g2, g3);
        }
        __syncthreads();

        // scatter with run-length pre-reduction (edges sorted by row)
        {
            int oct = tid & 15;        // edge octet (8 edges)
            int chunk = tid >> 4;      // feature 16B chunk 0..15
            int rprev = rs[oct * 8];
            float4 av = make_float4(0.f, 0.f, 0.f, 0.f);
#pragma unroll
            for (int j = 0; j < 8; j++) {
                int ee = oct * 8 + j;
                int rr = rs[ee];
                float v0 = ins[sidx(4 * chunk + 0, ee, 128)];
                float v1 = ins[sidx(4 * chunk + 1, ee, 128)];
                float v2 = ins[sidx(4 * chunk + 2, ee, 128)];
                float v3 = ins[sidx(4 * chunk + 3, ee, 128)];
                if (rr != rprev) {
                    red4(&g_agg[rprev * 64 + chunk * 4], av.x, av.y, av.z, av.w);
                    av = make_float4(v0, v1, v2, v3);
                    rprev = rr;
                } else {
                    av.x += v0;
                    av.y += v1;
                    av.z += v2;
                    av.w += v3;
                }
            }
            red4(&g_agg[rprev * 64 + chunk * 4], av.x, av.y, av.z, av.w);
        }
        if (tid < 16) {
            int oct = tid;
            int rprev = rs[oct * 8];
            float4 a4 = make_float4(0.f, 0.f, 0.f, 0.f);
#pragma unroll
            for (int j = 0; j < 8; j++) {
                int ee = oct * 8 + j;
                int rr = rs[ee];
                float gg = 0.f;
#pragma unroll
                for (int w8 = 0; w8 < 8; w8++) gg += part[w8 * 128 + ee];
                float gx = cds[ee] * gg, gy = cds[128 + ee] * gg, gz = cds[256 + ee] * gg;
                if (rr != rprev) {
                    red4(&g_acc4[rprev * 4], a4.x, a4.y, a4.z, a4.w);
                    a4 = make_float4(gx, gy, gz, 1.0f);
                    rprev = rr;
                } else {
                    a4.x += gx;
                    a4.y += gy;
                    a4.z += gz;
                    a4.w += 1.0f;
                }
            }
            red4(&g_acc4[rprev * 4], a4.x, a4.y, a4.z, a4.w);
        }
    }
}

// ======== 4-pair GEMM micro-kernel (node/proj; RW=64) ========
template <int RW>
__device__ __forceinline__ void gemm_t(const float* __restrict__ st,
                                       const float* __restrict__ w,
                                       const float* __restrict__ bias,
                                       ull (&acc)[4][4], int fc, int er, int K) {
#pragma unroll
    for (int j = 0; j < 4; j++) {
        ull bb = d2(bias[4 * fc + j]);
#pragma unroll
        for (int p = 0; p < 4; p++) acc[p][j] = bb;
    }
    const int eg0 = 2 * er, eg1 = 2 * er + 1;
#pragma unroll 2
    for (int k0 = 0; k0 < K; k0 += 4) {
        int ss = (k0 >> 2) & 7;
        int o0 = ((eg0 ^ ss) << 2), o1 = ((eg1 ^ ss) << 2);
#pragma unroll
        for (int kk = 0; kk < 4; kk++) {
            const float* rp = st + (k0 + kk) * RW;
            ulonglong2 aA = *(const ulonglong2*)(rp + o0);
            ulonglong2 aB = *(const ulonglong2*)(rp + o1);
            float4 wv = *(const float4*)(w + (k0 + kk) * 64 + 4 * fc);
            ull b0 = d2(wv.x), b1 = d2(wv.y), b2 = d2(wv.z), b3 = d2(wv.w);
            acc[0][0] = ffma2(aA.x, b0, acc[0][0]);
            acc[1][0] = ffma2(aA.y, b0, acc[1][0]);
            acc[2][0] = ffma2(aB.x, b0, acc[2][0]);
            acc[3][0] = ffma2(aB.y, b0, acc[3][0]);
            acc[0][1] = ffma2(aA.x, b1, acc[0][1]);
            acc[1][1] = ffma2(aA.y, b1, acc[1][1]);
            acc[2][1] = ffma2(aB.x, b1, acc[2][1]);
            acc[3][1] = ffma2(aB.y, b1, acc[3][1]);
            acc[0][2] = ffma2(aA.x, b2, acc[0][2]);
            acc[1][2] = ffma2(aA.y, b2, acc[1][2]);
            acc[2][2] = ffma2(aB.x, b2, acc[2][2]);
            acc[3][2] = ffma2(aB.y, b2, acc[3][2]);
            acc[0][3] = ffma2(aA.x, b3, acc[0][3]);
            acc[1][3] = ffma2(aA.y, b3, acc[1][3]);
            acc[2][3] = ffma2(aB.x, b3, acc[2][3]);
            acc[3][3] = ffma2(aB.y, b3, acc[3][3]);
        }
    }
}

template <int RW>
__device__ __forceinline__ void store_silu_t4(float* st, ull (&acc)[4][4], int fc, int er) {
    int ss = fc & 7;
    int o0 = (((2 * er) ^ ss) << 2), o1 = (((2 * er + 1) ^ ss) << 2);
#pragma unroll
    for (int j = 0; j < 4; j++) {
        int r = 4 * fc + j;
        float2 f0 = u2f(acc[0][j]), f1 = u2f(acc[1][j]);
        float2 f2 = u2f(acc[2][j]), f3 = u2f(acc[3][j]);
        float4 v0 = make_float4(silu_f(f0.x), silu_f(f0.y), silu_f(f1.x), silu_f(f1.y));
        float4 v1 = make_float4(silu_f(f2.x), silu_f(f2.y), silu_f(f3.x), silu_f(f3.y));
        *(float4*)(st + r * RW + o0) = v0;
        *(float4*)(st + r * RW + o1) = v1;
    }
}

// ---------------- proj kernel (initial only) ----------------
__global__ void __launch_bounds__(128, 2)
    k_proj(const float* __restrict__ ew1) {
    extern __shared__ __align__(16) float sm[];
    float* us = sm;             // 64*64

    const int tid = threadIdx.x;
    const int fc = tid & 15;
    const int er = tid >> 4;
    const int e = tid & 63;
    const int half = tid >> 6;

    const int ntile = (NN + TNN - 1) / TNN;
    for (int t = blockIdx.x; t < ntile; t += gridDim.x) {
        __syncthreads();
        int n0 = t * TNN;
        int n = n0 + e;
#pragma unroll
        for (int q = 0; q < 8; q++) {
            int kq = half * 8 + q;
            float4 hv = make_float4(0, 0, 0, 0);
            if (n < NN) hv = *(const float4*)&g_h[n * 64 + 4 * kq];
            us[sidx(4 * kq + 0, e, 64)] = hv.x;
            us[sidx(4 * kq + 1, e, 64)] = hv.y;
            us[sidx(4 * kq + 2, e, 64)] = hv.z;
            us[sidx(4 * kq + 3, e, 64)] = hv.w;
        }
        __syncthreads();

        ull acc[4][4];
        gemm_t<64>(us, ew1, g_zero64, acc, fc, er, 64);
#pragma unroll
        for (int p = 0; p < 4; p++) {
            int nlo = n0 + 8 * er + 2 * p, nhi = nlo + 1;
#pragma unroll
            for (int j = 0; j < 4; j++) {
                float2 f = u2f(acc[p][j]);
                if (nlo < NN) g_pa[nlo * 64 + 4 * fc + j] = f.x;
                if (nhi < NN) g_pa[nhi * 64 + 4 * fc + j] = f.y;
            }
        }
        gemm_t<64>(us, ew1 + 4096, g_zero64, acc, fc, er, 64);
#pragma unroll
        for (int p = 0; p < 4; p++) {
            int nlo = n0 + 8 * er + 2 * p, nhi = nlo + 1;
#pragma unroll
            for (int j = 0; j < 4; j++) {
                float2 f = u2f(acc[p][j]);
                if (nlo < NN) g_pb[nlo * 64 + 4 * fc + j] = f.x;
                if (nhi < NN) g_pb[nhi * 64 + 4 * fc + j] = f.y;
            }
        }
    }
}

// ---------------- node kernel (R9 verbatim): MLPs + update + fused proj ----------------
__global__ void __launch_bounds__(128, 2)
    k_node(const float* __restrict__ nw1, const float* __restrict__ nb1,
           const float* __restrict__ nw2, const float* __restrict__ nb2,
           const float* __restrict__ vw1, const float* __restrict__ vb1,
           const float* __restrict__ vw2, const float* __restrict__ vb2,
           const float* __restrict__ ew1) {
    extern __shared__ __align__(16) float sm[];
    float* wn1 = sm;
    float* wn2 = wn1 + 8192;
    float* wv1 = wn2 + 4096;
    float* us = wv1 + 4096;
    float* nb1s = us + 8192;
    float* nb2s = nb1s + 64;
    float* vb1s = nb2s + 64;
    float* vw2s = vb1s + 64;
    float* phis = vw2s + 64;

    const int tid = threadIdx.x;
    const int fc = tid & 15;
    const int er = tid >> 4;

    for (int i = tid; i < 2048; i += 128) ((float4*)wn1)[i] = ((const float4*)nw1)[i];
    for (int i = tid; i < 1024; i += 128) {
        ((float4*)wn2)[i] = ((const float4*)nw2)[i];
        ((float4*)wv1)[i] = ((const float4*)vw1)[i];
    }
    if (tid < 64) {
        nb1s[tid] = nb1[tid];
        nb2s[tid] = nb2[tid];
        vb1s[tid] = vb1[tid];
        vw2s[tid] = vw2[tid];
    }
    const float vb2v = vb2[0];

    const int e = tid & 63;
    const int half = tid >> 6;
    const int ntile = (NN + TNN - 1) / TNN;
    for (int t = blockIdx.x; t < ntile; t += gridDim.x) {
        __syncthreads();
        int n0 = t * TNN;
        int n = n0 + e;
#pragma unroll
        for (int q = 0; q < 8; q++) {
            int kq = half * 8 + q;
            float4 hv = make_float4(0, 0, 0, 0), av = make_float4(0, 0, 0, 0);
            if (n < NN) {
                hv = *(const float4*)&g_h[n * 64 + 4 * kq];
                av = *(const float4*)&g_agg[n * 64 + 4 * kq];
            }
            us[sidx(4 * kq + 0, e, 64)] = hv.x;
            us[sidx(4 * kq + 1, e, 64)] = hv.y;
            us[sidx(4 * kq + 2, e, 64)] = hv.z;
            us[sidx(4 * kq + 3, e, 64)] = hv.w;
            us[sidx(64 + 4 * kq + 0, e, 64)] = av.x;
            us[sidx(64 + 4 * kq + 1, e, 64)] = av.y;
            us[sidx(64 + 4 * kq + 2, e, 64)] = av.z;
            us[sidx(64 + 4 * kq + 3, e, 64)] = av.w;
        }
        __syncthreads();

        ull acc[4][4];
        // vel MLP
        gemm_t<64>(us, wv1, vb1s, acc, fc, er, 64);
        {
            float gv[8] = {0.f, 0.f, 0.f, 0.f, 0.f, 0.f, 0.f, 0.f};
#pragma unroll
            for (int p = 0; p < 4; p++)
#pragma unroll
                for (int j = 0; j < 4; j++) {
                    float2 f = u2f(acc[p][j]);
                    float cj = vw2s[4 * fc + j];
                    gv[2 * p] = fmaf(silu_f(f.x), cj, gv[2 * p]);
                    gv[2 * p + 1] = fmaf(silu_f(f.y), cj, gv[2 * p + 1]);
                }
#pragma unroll
            for (int m = 1; m < 16; m <<= 1)
#pragma unroll
                for (int i = 0; i < 8; i++)
                    gv[i] += __shfl_xor_sync(0xffffffffu, gv[i], m);
            if (fc == 0)
#pragma unroll
                for (int i = 0; i < 8; i++) phis[8 * er + i] = gv[i] + vb2v;
        }

        // node GEMM1
        gemm_t<64>(us, wn1, nb1s, acc, fc, er, 128);
        __syncthreads();
        store_silu_t4<64>(us + 64 * 64, acc, fc, er);
        __syncthreads();

        // node GEMM2 -> hn; h += hn; restage h_new
        gemm_t<64>(us + 64 * 64, wn2, nb2s, acc, fc, er, 64);
#pragma unroll
        for (int p = 0; p < 4; p++) {
            int nlo = n0 + 8 * er + 2 * p, nhi = nlo + 1;
#pragma unroll
            for (int j = 0; j < 4; j++) {
                float2 f = u2f(acc[p][j]);
                if (nlo < NN) {
                    float hx = g_h[nlo * 64 + 4 * fc + j] + f.x;
                    g_h[nlo * 64 + 4 * fc + j] = hx;
                    us[sidx(4 * fc + j, 8 * er + 2 * p, 64)] = hx;
                }
                if (nhi < NN) {
                    float hx = g_h[nhi * 64 + 4 * fc + j] + f.y;
                    g_h[nhi * 64 + 4 * fc + j] = hx;
                    us[sidx(4 * fc + j, 8 * er + 2 * p + 1, 64)] = hx;
                }
            }
        }

        // per-node coord/vel update + zero scratch
        if (tid < TNN) {
            int nu = n0 + tid;
            if (nu < NN) {
                float cnt = g_acc4[nu * 4 + 3];
                float inv = 1.0f / fmaxf(cnt, 1.0f);
                float phi = phis[tid];
#pragma unroll
                for (int d = 0; d < 3; d++) {
                    float a = g_acc4[nu * 4 + d] * inv;
                    float vn = g_v[nu * 3 + d] + a + phi * g_iv[nu * 3 + d];
                    g_v[nu * 3 + d] = vn;
                    g_x[nu * 3 + d] += vn;
                }
                *(float4*)&g_acc4[nu * 4] = make_float4(0.f, 0.f, 0.f, 0.f);
            }
        }
        for (int i = tid; i < TNN * 64; i += 128) {
            int nz = n0 + (i >> 6);
            if (nz < NN) g_agg[nz * 64 + (i & 63)] = 0.f;
        }
        __syncthreads();

        // fused proj: Pa/Pb from h_new
        gemm_t<64>(us, ew1, g_zero64, acc, fc, er, 64);
#pragma unroll
        for (int p = 0; p < 4; p++) {
            int nlo = n0 + 8 * er + 2 * p, nhi = nlo + 1;
#pragma unroll
            for (int j = 0; j < 4; j++) {
                float2 f = u2f(acc[p][j]);
                if (nlo < NN) g_pa[nlo * 64 + 4 * fc + j] = f.x;
                if (nhi < NN) g_pa[nhi * 64 + 4 * fc + j] = f.y;
            }
        }
        gemm_t<64>(us, ew1 + 4096, g_zero64, acc, fc, er, 64);
#pragma unroll
        for (int p = 0; p < 4; p++) {
            int nlo = n0 + 8 * er + 2 * p, nhi = nlo + 1;
#pragma unroll
            for (int j = 0; j < 4; j++) {
                float2 f = u2f(acc[p][j]);
                if (nlo < NN) g_pb[nlo * 64 + 4 * fc + j] = f.x;
                if (nhi < NN) g_pb[nhi * 64 + 4 * fc + j] = f.y;
            }
        }
    }
}

// ---------------- output: [x | h | v] ----------------
__global__ void k_copyout(float* __restrict__ out) {
    int i = blockIdx.x * blockDim.x + threadIdx.x;
    if (i < NN * 3) out[i] = g_x[i];
    if (i < NN * HD) out[NN * 3 + i] = g_h[i];
    if (i < NN * 3) out[NN * 3 + NN * HD + i] = g_v[i];
}

extern "C" void kernel_launch(void* const* d_in, const int* in_sizes, int n_in,
                              void* d_out, int out_size) {
    const float* his = (const float*)d_in[0];
    const float* loc = (const float*)d_in[1];
    const void* edges = d_in[2];
    const float* vel = (const float*)d_in[3];
    const float* eattr = (const float*)d_in[4];
    const float* emb_w = (const float*)d_in[5];
    const float* emb_b = (const float*)d_in[6];
    const float* ew1 = (const float*)d_in[7];
    const float* eb1 = (const float*)d_in[8];
    const float* ew2 = (const float*)d_in[9];
    const float* eb2 = (const float*)d_in[10];
    const float* nw1 = (const float*)d_in[11];
    const float* nb1 = (const float*)d_in[12];
    const float* nw2 = (const float*)d_in[13];
    const float* nb2 = (const float*)d_in[14];
    const float* cw1 = (const float*)d_in[15];
    const float* cb1 = (const float*)d_in[16];
    const float* cw2 = (const float*)d_in[17];
    const float* vw1 = (const float*)d_in[18];
    const float* vb1 = (const float*)d_in[19];
    const float* vw2 = (const float*)d_in[20];
    const float* vb2 = (const float*)d_in[21];

    size_t esm = (size_t)(8192 + 1024 + 256 + 192 + 384) * 4 + 128 * sizeof(int);
    size_t nsm = (size_t)(8192 + 4096 + 4096 + 8192 + 4 * 64 + 64) * 4;
    size_t psm = (size_t)4096 * 4;
    cudaFuncSetAttribute(k_edge, cudaFuncAttributeMaxDynamicSharedMemorySize, (int)esm);
    cudaFuncSetAttribute(k_node, cudaFuncAttributeMaxDynamicSharedMemorySize, (int)nsm);
    cudaFuncSetAttribute(k_proj, cudaFuncAttributeMaxDynamicSharedMemorySize, (int)psm);

    k_detect<<<1, 1>>>(edges);
    k_zhist<<<(NN + 255) / 256, 256>>>();
    k_count<<<(NE + 255) / 256, 256>>>(edges);
    k_scan<<<1, 1024>>>();
    k_permute<<<(NE + 255) / 256, 256>>>(edges, eattr);
    k_init<<<(NN * HD + 255) / 256, 256>>>(his, loc, vel, emb_w, emb_b);
    k_proj<<<157, 128, psm>>>(ew1);
    for (int l = 0; l < NLAYERS; l++) {
        k_edge<<<444, 256, esm>>>(ew1, eb1, ew2, eb2, cw1, cb1, cw2);
        k_node<<<157, 128, nsm>>>(nw1, nb1, nw2, nb2, vw1, vb1, vw2, vb2, ew1);
    }
    k_copyout<<<(NN * HD + 255) / 256, 256>>>((float*)d_out);
}